// round 10
// baseline (speedup 1.0000x reference)
#include <cuda_runtime.h>
#include <cuda_bf16.h>
#include <mma.h>
#include <cstdint>

using namespace nvcuda;

// EGCL: N_NODES=20000, N_EDGES=640000, FEAT=HID=128
#define TPB   512
#define HID   128
#define MAXN  20000
#define TILE  128

#define AST   136                 // bf16 image stride; 272B mod 128 = 16 -> conflict-free LDSM
#define CST   132                 // float C stride; 528B
#define IMG_B (128 * AST * 2)     // 34816 B per bf16 image
#define PANEL_B (2 * IMG_B)       // 69632 B per weight panel (hi+lo)

// ---------------- device scratch ----------------
__device__ float g_magg [(size_t)MAXN * HID];
__device__ float g_shift[(size_t)MAXN * 3];
// 9 panels: 0=pe_w0[0:128) 1=pe_w0[128:256) 2=pe_w1 3=px_w0 4=px_w1
//           5=ph_w0[0:128) 6=ph_w0[128:256) 7=ph_w1 8=ph_w2
__device__ unsigned char g_wimg[9 * PANEL_B];

// ---------------- helpers ----------------
__device__ __forceinline__ float tanh_ap(float x){
    float t; asm("tanh.approx.f32 %0, %1;" : "=f"(t) : "f"(x)); return t;
}
__device__ __forceinline__ float silu_f(float x){
    float t = tanh_ap(0.5f * x);
    return fmaf(0.5f * x, t, 0.5f * x);
}
__device__ __forceinline__ float sigmoid_f(float x){
    return fmaf(0.5f, tanh_ap(0.5f * x), 0.5f);
}
__device__ __forceinline__ void red4(float* p, float a, float b, float c, float d){
    asm volatile("red.global.add.v4.f32 [%0], {%1,%2,%3,%4};"
                 :: "l"(p), "f"(a), "f"(b), "f"(c), "f"(d) : "memory");
}
__device__ __forceinline__ uint32_t smem_u32(const void* p){
    uint32_t a; asm("{ .reg .u64 t; cvta.to.shared.u64 t, %1; cvt.u32.u64 %0, t; }" : "=r"(a) : "l"(p));
    return a;
}
// pack 2 floats -> bf16x2 hi + bf16x2 lo (split precision)
__device__ __forceinline__ uint32_t pack2(float a, float b, uint32_t &l2){
    uint32_t h2; asm("cvt.rn.bf16x2.f32 %0, %1, %2;" : "=r"(h2) : "f"(b), "f"(a));
    float fa = __uint_as_float(h2 << 16);
    float fb = __uint_as_float(h2 & 0xffff0000u);
    float ra = a - fa, rb = b - fb;
    asm("cvt.rn.bf16x2.f32 %0, %1, %2;" : "=r"(l2) : "f"(rb), "f"(ra));
    return h2;
}
__device__ __forceinline__ uint32_t pack2h(float a, float b){
    uint32_t h2; asm("cvt.rn.bf16x2.f32 %0, %1, %2;" : "=r"(h2) : "f"(b), "f"(a));
    return h2;
}
#define CP_COMMIT()  asm volatile("cp.async.commit_group;" ::: "memory")
#define CP_WAIT(n)   asm volatile("cp.async.wait_group %0;" :: "n"(n) : "memory")

// ---------------- wmma ----------------
typedef wmma::fragment<wmma::matrix_a, 16,16,16, __nv_bfloat16, wmma::row_major> FragA;
typedef wmma::fragment<wmma::matrix_b, 16,16,16, __nv_bfloat16, wmma::row_major> FragB;
typedef wmma::fragment<wmma::accumulator, 16,16,16, float> FragC;

__device__ __forceinline__ void fill0(FragC (&acc)[2][2]){
    #pragma unroll
    for (int mt = 0; mt < 2; mt++)
        #pragma unroll
        for (int nt = 0; nt < 2; nt++)
            wmma::fill_fragment(acc[mt][nt], 0.0f);
}

// K=128 GEMM, 3 bf16 products. warp tile 32x32: rows wr*32.., cols wc*32..
__device__ __forceinline__ void gemm_step3(const __nv_bfloat16* Ah, const __nv_bfloat16* Al,
                                           const unsigned char* panel,
                                           FragC (&acc)[2][2], int wr, int wc){
    const __nv_bfloat16* Bh = (const __nv_bfloat16*)panel;
    const __nv_bfloat16* Bl = (const __nv_bfloat16*)(panel + IMG_B);
    #pragma unroll
    for (int kt = 0; kt < 8; kt++){
        FragA ah[2], al[2];
        #pragma unroll
        for (int mt = 0; mt < 2; mt++){
            int row = wr * 32 + mt * 16;
            wmma::load_matrix_sync(ah[mt], Ah + row * AST + kt * 16, AST);
            wmma::load_matrix_sync(al[mt], Al + row * AST + kt * 16, AST);
        }
        #pragma unroll
        for (int nt = 0; nt < 2; nt++){
            int col = wc * 32 + nt * 16;
            FragB bh, bl;
            wmma::load_matrix_sync(bh, Bh + kt * 16 * AST + col, AST);
            wmma::load_matrix_sync(bl, Bl + kt * 16 * AST + col, AST);
            #pragma unroll
            for (int mt = 0; mt < 2; mt++){
                wmma::mma_sync(acc[mt][nt], ah[mt], bh, acc[mt][nt]);
                wmma::mma_sync(acc[mt][nt], ah[mt], bl, acc[mt][nt]);
                wmma::mma_sync(acc[mt][nt], al[mt], bh, acc[mt][nt]);
            }
        }
    }
}

// K=128 GEMM, 1 bf16 product (phi_x branch: error diluted ~2.5e-5x into output)
__device__ __forceinline__ void gemm_step1(const __nv_bfloat16* Ah,
                                           const unsigned char* panel,
                                           FragC (&acc)[2][2], int wr, int wc){
    const __nv_bfloat16* Bh = (const __nv_bfloat16*)panel;
    #pragma unroll
    for (int kt = 0; kt < 8; kt++){
        FragA ah[2];
        #pragma unroll
        for (int mt = 0; mt < 2; mt++)
            wmma::load_matrix_sync(ah[mt], Ah + (wr*32 + mt*16) * AST + kt * 16, AST);
        #pragma unroll
        for (int nt = 0; nt < 2; nt++){
            FragB bh;
            wmma::load_matrix_sync(bh, Bh + kt * 16 * AST + wc * 32 + nt * 16, AST);
            #pragma unroll
            for (int mt = 0; mt < 2; mt++)
                wmma::mma_sync(acc[mt][nt], ah[mt], bh, acc[mt][nt]);
        }
    }
}

__device__ __forceinline__ void store_c(float* C, FragC (&acc)[2][2], int wr, int wc){
    #pragma unroll
    for (int mt = 0; mt < 2; mt++)
        #pragma unroll
        for (int nt = 0; nt < 2; nt++)
            wmma::store_matrix_sync(C + (wr*32 + mt*16) * CST + wc*32 + nt*16,
                                    acc[mt][nt], CST, wmma::mem_row_major);
}

// cp.async one 69632B panel, 512 threads
__device__ __forceinline__ void cp_panel(uint32_t dst, const unsigned char* src, int tid){
    for (int o = tid * 16; o < PANEL_B; o += TPB * 16)
        asm volatile("cp.async.cg.shared.global [%0], [%1], 16;"
                     :: "r"(dst + o), "l"(src + o) : "memory");
}

// scaled 32-col quarter-row -> A hi/lo images at (r, q). src pre-offset by q*32.
__device__ __forceinline__ void gather_row(__nv_bfloat16* Ah, __nv_bfloat16* Al,
                                           const float* __restrict__ src, float sc,
                                           int r, int q){
    uint32_t* ih = (uint32_t*)(Ah + r * AST + q * 32);
    uint32_t* il = (uint32_t*)(Al + r * AST + q * 32);
    #pragma unroll
    for (int g = 0; g < 4; g++){
        float4 v0 = __ldg((const float4*)src + 2*g);
        float4 v1 = __ldg((const float4*)src + 2*g + 1);
        uint4 hi, lo;
        hi.x = pack2(v0.x*sc, v0.y*sc, lo.x);
        hi.y = pack2(v0.z*sc, v0.w*sc, lo.y);
        hi.z = pack2(v1.x*sc, v1.y*sc, lo.z);
        hi.w = pack2(v1.z*sc, v1.w*sc, lo.w);
        *(uint4*)(ih + g*4) = hi;
        *(uint4*)(il + g*4) = lo;
    }
}

// epilogue hi+lo (feeds 3-product). bias/wlen pre-offset by q*32.
__device__ __forceinline__ void epi_act(const float* C, const float* bias, const float* wlen,
                                        float lenr, __nv_bfloat16* Ah, __nv_bfloat16* Al,
                                        int r, int q){
    const float* crow = C + r * CST + q * 32;
    uint32_t* ih = (uint32_t*)(Ah + r * AST + q * 32);
    uint32_t* il = (uint32_t*)(Al + r * AST + q * 32);
    #pragma unroll
    for (int g = 0; g < 4; g++){
        float f[8];
        #pragma unroll
        for (int j = 0; j < 8; j++){
            int c = g * 8 + j;
            float x = crow[c] + bias[c];
            if (wlen) x += lenr * wlen[c];
            f[j] = silu_f(x);
        }
        uint4 hi, lo;
        hi.x = pack2(f[0], f[1], lo.x);
        hi.y = pack2(f[2], f[3], lo.y);
        hi.z = pack2(f[4], f[5], lo.z);
        hi.w = pack2(f[6], f[7], lo.w);
        *(uint4*)(ih + g*4) = hi;
        *(uint4*)(il + g*4) = lo;
    }
}

// epilogue hi only (feeds 1-product)
__device__ __forceinline__ void epi_act_hi(const float* C, const float* bias,
                                           __nv_bfloat16* Ah, int r, int q){
    const float* crow = C + r * CST + q * 32;
    uint32_t* ih = (uint32_t*)(Ah + r * AST + q * 32);
    #pragma unroll
    for (int g = 0; g < 4; g++){
        float f[8];
        #pragma unroll
        for (int j = 0; j < 8; j++)
            f[j] = silu_f(crow[g*8+j] + bias[g*8+j]);
        uint4 hi;
        hi.x = pack2h(f[0], f[1]);
        hi.y = pack2h(f[2], f[3]);
        hi.z = pack2h(f[4], f[5]);
        hi.w = pack2h(f[6], f[7]);
        *(uint4*)(ih + g*4) = hi;
    }
}

// ---------------- zero / prep ----------------
__global__ void zero_kernel(int N){
    const int i = blockIdx.x * blockDim.x + threadIdx.x;
    const int stride = gridDim.x * blockDim.x;
    const int m4 = N * (HID / 4);
    float4 z4 = make_float4(0.f, 0.f, 0.f, 0.f);
    for (int j = i; j < m4; j += stride) ((float4*)g_magg)[j] = z4;
    for (int j = i; j < 3 * N; j += stride) g_shift[j] = 0.0f;
}

__global__ void prep_kernel(const float* __restrict__ pe_w0, const float* __restrict__ pe_w1,
                            const float* __restrict__ px_w0, const float* __restrict__ px_w1,
                            const float* __restrict__ ph_w0, const float* __restrict__ ph_w1,
                            const float* __restrict__ ph_w2){
    int i = blockIdx.x * blockDim.x + threadIdx.x;   // 9 * 128 * 128
    if (i >= 9 * 128 * 128) return;
    int p = i >> 14, rem = i & 16383, n = rem >> 7, k = rem & 127;
    const float* W; int krow = k;
    switch (p){ case 0: W = pe_w0; break;
                case 1: W = pe_w0; krow = k + 128; break;
                case 2: W = pe_w1; break;
                case 3: W = px_w0; break;
                case 4: W = px_w1; break;
                case 5: W = ph_w0; break;
                case 6: W = ph_w0; krow = k + 128; break;
                case 7: W = ph_w1; break;
                default: W = ph_w2; }
    float w = __ldg(W + krow * HID + n);
    __nv_bfloat16 h = __float2bfloat16(w);
    __nv_bfloat16 l = __float2bfloat16(w - __bfloat162float(h));
    unsigned char* base = g_wimg + p * PANEL_B;
    *(__nv_bfloat16*)(base + (k * AST + n) * 2) = h;
    *(__nv_bfloat16*)(base + IMG_B + (k * AST + n) * 2) = l;
}

// ---------------- shared smem layout (bytes) ----------------
#define OFF_A     0
#define OFF_S0    69632
#define OFF_S1    139264
#define OFF_CONST 208896   // 7 x 512B const slots
#define OFF_LEN   212480
#define OFF_VX    212992
#define OFF_VY    213504
#define OFF_VZ    214016
#define OFF_RIDX  214528
#define OFF_SIDX  215040
#define OFF_MISC  215552
#define EDGE_SMEM 215560

// ---------------- edge kernel ----------------
__global__ void __launch_bounds__(TPB, 1) edge_kernel(
    const float* __restrict__ pos,   const float* __restrict__ feat,
    const float* __restrict__ pe_w0,
    const float* __restrict__ pe_b0, const float* __restrict__ pe_b1,
    const float* __restrict__ px_b0, const float* __restrict__ px_b1,
    const float* __restrict__ px_ow, const float* __restrict__ px_ob,
    const float* __restrict__ e_w,   const float* __restrict__ e_b,
    const int* __restrict__ senders, const int* __restrict__ recv, int E)
{
    extern __shared__ unsigned char sm[];
    const int tid = threadIdx.x;
    const int wid = tid >> 5;
    const int wr = wid & 3, wc = wid >> 2;     // 4x4 warp grid, 32x32 tiles
    const int ebase = blockIdx.x * TILE;

    __nv_bfloat16* Ah = (__nv_bfloat16*)(sm + OFF_A);
    __nv_bfloat16* Al = (__nv_bfloat16*)(sm + OFF_A + IMG_B);
    float* c_pe_b0 = (float*)(sm + OFF_CONST);
    float* c_pe_b1 = (float*)(sm + OFF_CONST + 512);
    float* c_px_b0 = (float*)(sm + OFF_CONST + 1024);
    float* c_px_b1 = (float*)(sm + OFF_CONST + 1536);
    float* c_wlen  = (float*)(sm + OFF_CONST + 2048);
    float* c_pxow  = (float*)(sm + OFF_CONST + 2560);
    float* c_ew    = (float*)(sm + OFF_CONST + 3072);
    float* s_len   = (float*)(sm + OFF_LEN);
    float* s_vx    = (float*)(sm + OFF_VX);
    float* s_vy    = (float*)(sm + OFF_VY);
    float* s_vz    = (float*)(sm + OFF_VZ);
    int*   s_ridx  = (int*)  (sm + OFF_RIDX);
    int*   s_sidx  = (int*)  (sm + OFF_SIDX);
    float* s_misc  = (float*)(sm + OFF_MISC);

    const uint32_t smb = smem_u32(sm);

    cp_panel(smb + OFF_S0, g_wimg,           tid); CP_COMMIT();   // pe_w0 top
    cp_panel(smb + OFF_S1, g_wimg + PANEL_B, tid); CP_COMMIT();   // pe_w0 mid

    if (tid < 128){
        int e = ebase + tid;
        int ec = (e < E) ? e : 0;
        int s = __ldg(senders + ec), r = __ldg(recv + ec);
        float vx = __ldg(pos + 3*r + 0) - __ldg(pos + 3*s + 0);
        float vy = __ldg(pos + 3*r + 1) - __ldg(pos + 3*s + 1);
        float vz = __ldg(pos + 3*r + 2) - __ldg(pos + 3*s + 2);
        float n2 = vx*vx + vy*vy + vz*vz;
        s_len[tid] = (n2 > 0.0f) ? sqrtf(n2) : 0.0f;
        s_vx[tid] = vx; s_vy[tid] = vy; s_vz[tid] = vz;
        s_ridx[tid] = r; s_sidx[tid] = s;
    } else if (tid < 256){
        int i = tid - 128;
        c_pe_b0[i] = __ldg(pe_b0 + i);
        c_pe_b1[i] = __ldg(pe_b1 + i);
        c_px_b0[i] = __ldg(px_b0 + i);
        c_px_b1[i] = __ldg(px_b1 + i);
        c_wlen[i]  = __ldg(pe_w0 + 256 * HID + i);
        c_pxow[i]  = __ldg(px_ow + i);
        c_ew[i]    = __ldg(e_w + i);
        if (i == 0){ s_misc[0] = __ldg(e_b); s_misc[1] = __ldg(px_ob); }
    }
    __syncthreads();

    const int r  = tid >> 2;          // 128 rows
    const int q  = tid & 3;           // quarter (32 cols)
    const bool on = (ebase + r < E);

    // ---- layer 1 (K=256 over two GEMMs) ----
    gather_row(Ah, Al, feat + (size_t)s_sidx[r] * HID + q*32, 1.0f, r, q);
    CP_WAIT(1);
    __syncthreads();

    FragC acc[2][2];
    fill0(acc);
    gemm_step3(Ah, Al, sm + OFF_S0, acc, wr, wc);
    __syncthreads();

    gather_row(Ah, Al, feat + (size_t)s_ridx[r] * HID + q*32, 1.0f, r, q);
    cp_panel(smb + OFF_S0, g_wimg + 2*PANEL_B, tid); CP_COMMIT();  // pe_w1
    CP_WAIT(1);
    __syncthreads();

    gemm_step3(Ah, Al, sm + OFF_S1, acc, wr, wc);
    __syncthreads();
    store_c((float*)(sm + OFF_S1), acc, wr, wc);
    __syncthreads();

    // epi1: act1 = silu(C + pe_b0 + len*w_len) -> A (hi+lo)
    epi_act((float*)(sm + OFF_S1), c_pe_b0 + q*32, c_wlen + q*32,
            s_len[r], Ah, Al, r, q);
    __syncthreads();
    cp_panel(smb + OFF_S1, g_wimg + 3*PANEL_B, tid); CP_COMMIT();  // px_w0
    CP_WAIT(1);
    __syncthreads();

    // ---- layer 2: m ----
    fill0(acc);
    gemm_step3(Ah, Al, sm + OFF_S0, acc, wr, wc);
    __syncthreads();
    store_c((float*)(sm + OFF_S0), acc, wr, wc);
    __syncthreads();

    // epi2: m, gate, RED aggregation; m -> A (hi only)
    {
        const float* crow = (float*)(sm + OFF_S0) + r * CST + q * 32;
        const float* bias = c_pe_b1 + q * 32;
        const float* ew   = c_ew    + q * 32;
        uint32_t* ih = (uint32_t*)(Ah + r * AST + q * 32);
        float m[32];
        float g = 0.0f;
        #pragma unroll
        for (int gq = 0; gq < 4; gq++){
            #pragma unroll
            for (int j = 0; j < 8; j++){
                int c = gq * 8 + j;
                float v = silu_f(crow[c] + bias[c]);
                m[c] = v;
                g = fmaf(v, ew[c], g);
            }
            uint4 hi;
            int c0 = gq * 8;
            hi.x = pack2h(m[c0+0], m[c0+1]);
            hi.y = pack2h(m[c0+2], m[c0+3]);
            hi.z = pack2h(m[c0+4], m[c0+5]);
            hi.w = pack2h(m[c0+6], m[c0+7]);
            *(uint4*)(ih + gq*4) = hi;
        }
        g += __shfl_xor_sync(0xffffffffu, g, 1);
        g += __shfl_xor_sync(0xffffffffu, g, 2);
        float gate = sigmoid_f(g + s_misc[0]);
        if (on){
            float* mb = g_magg + (size_t)s_ridx[r] * HID + q * 32;
            #pragma unroll
            for (int j = 0; j < 32; j += 4)
                red4(mb + j, m[j]*gate, m[j+1]*gate, m[j+2]*gate, m[j+3]*gate);
        }
    }
    __syncthreads();
    cp_panel(smb + OFF_S0, g_wimg + 4*PANEL_B, tid); CP_COMMIT();  // px_w1
    CP_WAIT(1);
    __syncthreads();

    // ---- layer 3 (1-product) ----
    fill0(acc);
    gemm_step1(Ah, sm + OFF_S1, acc, wr, wc);
    __syncthreads();
    store_c((float*)(sm + OFF_S1), acc, wr, wc);
    __syncthreads();

    epi_act_hi((float*)(sm + OFF_S1), c_px_b0 + q*32, Ah, r, q);
    __syncthreads();
    CP_WAIT(0);
    __syncthreads();

    // ---- layer 4 (1-product) + Dense(1) head ----
    fill0(acc);
    gemm_step1(Ah, sm + OFF_S0, acc, wr, wc);
    __syncthreads();
    store_c((float*)(sm + OFF_S0), acc, wr, wc);
    __syncthreads();

    {
        const float* crow = (float*)(sm + OFF_S0) + r * CST + q * 32;
        const float* bias = c_px_b1 + q * 32;
        const float* pw   = c_pxow  + q * 32;
        float a = 0.0f;
        #pragma unroll
        for (int c = 0; c < 32; c++)
            a = fmaf(silu_f(crow[c] + bias[c]), pw[c], a);
        a += __shfl_xor_sync(0xffffffffu, a, 1);
        a += __shfl_xor_sync(0xffffffffu, a, 2);
        if (q == 0 && on){
            float phi = a + s_misc[1];
            float cc = __fdividef(phi, 1.0f + s_len[r]);
            atomicAdd(g_shift + 3*s_ridx[r] + 0, cc * s_vx[r]);
            atomicAdd(g_shift + 3*s_ridx[r] + 1, cc * s_vy[r]);
            atomicAdd(g_shift + 3*s_ridx[r] + 2, cc * s_vz[r]);
        }
    }
}

// ---------------- node kernel (wmma, same machinery) ----------------
__global__ void __launch_bounds__(TPB, 1) node_kernel(
    const float* __restrict__ pos,   const float* __restrict__ feat,
    const float* __restrict__ ph_b0, const float* __restrict__ ph_b1,
    const float* __restrict__ ph_b2,
    float* __restrict__ out, int N)
{
    extern __shared__ unsigned char sm[];
    const int tid = threadIdx.x;
    const int wid = tid >> 5;
    const int wr = wid & 3, wc = wid >> 2;
    const int base = blockIdx.x * TILE;

    __nv_bfloat16* Ah = (__nv_bfloat16*)(sm + OFF_A);
    __nv_bfloat16* Al = (__nv_bfloat16*)(sm + OFF_A + IMG_B);
    float* c_b0 = (float*)(sm + OFF_CONST);
    float* c_b1 = (float*)(sm + OFF_CONST + 512);
    float* c_b2 = (float*)(sm + OFF_CONST + 1024);

    const uint32_t smb = smem_u32(sm);

    cp_panel(smb + OFF_S0, g_wimg + 5*PANEL_B, tid); CP_COMMIT();   // ph_w0 top
    cp_panel(smb + OFF_S1, g_wimg + 6*PANEL_B, tid); CP_COMMIT();   // ph_w0 bottom

    if (tid < 128){
        c_b0[tid] = __ldg(ph_b0 + tid);
        c_b2[tid] = __ldg(ph_b2 + tid);
    } else if (tid < 256){
        c_b1[tid - 128] = __ldg(ph_b1 + tid - 128);
    }
    __syncthreads();

    const int r  = tid >> 2;
    const int q  = tid & 3;
    const int n  = base + r;
    const bool on = (n < N);
    const int nc = on ? n : (N - 1);
    const float inv_s = rsqrtf((float)(N - 1));

    // ---- layer 1 (K=256): [m_i*inv_s, h] @ ph_w0 ----
    gather_row(Ah, Al, g_magg + (size_t)nc * HID + q*32, inv_s, r, q);
    CP_WAIT(1);
    __syncthreads();

    FragC acc[2][2];
    fill0(acc);
    gemm_step3(Ah, Al, sm + OFF_S0, acc, wr, wc);
    __syncthreads();

    gather_row(Ah, Al, feat + (size_t)nc * HID + q*32, 1.0f, r, q);
    cp_panel(smb + OFF_S0, g_wimg + 7*PANEL_B, tid); CP_COMMIT();   // ph_w1
    CP_WAIT(1);
    __syncthreads();

    gemm_step3(Ah, Al, sm + OFF_S1, acc, wr, wc);
    __syncthreads();
    store_c((float*)(sm + OFF_S1), acc, wr, wc);
    __syncthreads();

    epi_act((float*)(sm + OFF_S1), c_b0 + q*32, nullptr, 0.0f, Ah, Al, r, q);
    __syncthreads();
    cp_panel(smb + OFF_S1, g_wimg + 8*PANEL_B, tid); CP_COMMIT();   // ph_w2
    CP_WAIT(1);
    __syncthreads();

    // ---- layer 2 ----
    fill0(acc);
    gemm_step3(Ah, Al, sm + OFF_S0, acc, wr, wc);
    __syncthreads();
    store_c((float*)(sm + OFF_S0), acc, wr, wc);
    __syncthreads();

    epi_act((float*)(sm + OFF_S0), c_b1 + q*32, nullptr, 0.0f, Ah, Al, r, q);
    __syncthreads();
    CP_WAIT(0);
    __syncthreads();

    // ---- layer 3 (no activation) ----
    fill0(acc);
    gemm_step3(Ah, Al, sm + OFF_S1, acc, wr, wc);
    __syncthreads();
    store_c((float*)(sm + OFF_S1), acc, wr, wc);
    __syncthreads();

    if (on){
        const float* crow = (float*)(sm + OFF_S1) + r * CST + q * 32;
        const float* bias = c_b2 + q * 32;
        const float* fr   = feat + (size_t)n * HID + q * 32;
        float* of = out + (size_t)3 * N + (size_t)n * HID + q * 32;
        #pragma unroll
        for (int g = 0; g < 8; g++){
            float4 f = __ldg((const float4*)fr + g);
            float4 o;
            o.x = crow[4*g+0] + bias[4*g+0] + f.x;
            o.y = crow[4*g+1] + bias[4*g+1] + f.y;
            o.z = crow[4*g+2] + bias[4*g+2] + f.z;
            o.w = crow[4*g+3] + bias[4*g+3] + f.w;
            *((float4*)of + g) = o;
        }
        if (q == 0){
            const float inv_n = 1.0f / (float)(N - 1);
            out[3*n+0] = __ldg(pos + 3*n + 0) + g_shift[3*n+0] * inv_n;
            out[3*n+1] = __ldg(pos + 3*n + 1) + g_shift[3*n+1] * inv_n;
            out[3*n+2] = __ldg(pos + 3*n + 2) + g_shift[3*n+2] * inv_n;
        }
    }
}

// ---------------- launcher ----------------
extern "C" void kernel_launch(void* const* d_in, const int* in_sizes, int n_in,
                              void* d_out, int out_size)
{
    const float* pos   = (const float*)d_in[0];
    const float* feat  = (const float*)d_in[1];
    const float* pe_w0 = (const float*)d_in[2];
    const float* pe_b0 = (const float*)d_in[3];
    const float* pe_w1 = (const float*)d_in[4];
    const float* pe_b1 = (const float*)d_in[5];
    const float* px_w0 = (const float*)d_in[6];
    const float* px_b0 = (const float*)d_in[7];
    const float* px_w1 = (const float*)d_in[8];
    const float* px_b1 = (const float*)d_in[9];
    const float* px_ow = (const float*)d_in[10];
    const float* px_ob = (const float*)d_in[11];
    const float* e_w   = (const float*)d_in[12];
    const float* e_b   = (const float*)d_in[13];
    const float* ph_w0 = (const float*)d_in[14];
    const float* ph_b0 = (const float*)d_in[15];
    const float* ph_w1 = (const float*)d_in[16];
    const float* ph_b1 = (const float*)d_in[17];
    const float* ph_w2 = (const float*)d_in[18];
    const float* ph_b2 = (const float*)d_in[19];
    const int* senders = (const int*)d_in[20];
    const int* recv    = (const int*)d_in[21];

    const int N = in_sizes[0] / 3;
    const int E = in_sizes[20];

    cudaFuncSetAttribute(edge_kernel, cudaFuncAttributeMaxDynamicSharedMemorySize, EDGE_SMEM);
    cudaFuncSetAttribute(node_kernel, cudaFuncAttributeMaxDynamicSharedMemorySize, EDGE_SMEM);

    zero_kernel<<<512, 256>>>(N);
    prep_kernel<<<(9*128*128 + 255)/256, 256>>>(pe_w0, pe_w1, px_w0, px_w1,
                                                ph_w0, ph_w1, ph_w2);
    edge_kernel<<<(E + TILE - 1)/TILE, TPB, EDGE_SMEM>>>(
        pos, feat, pe_w0, pe_b0, pe_b1, px_b0, px_b1,
        px_ow, px_ob, e_w, e_b, senders, recv, E);
    node_kernel<<<(N + TILE - 1)/TILE, TPB, EDGE_SMEM>>>(
        pos, feat, ph_b0, ph_b1, ph_b2, (float*)d_out, N);
}

// round 16
// speedup vs baseline: 1.3065x; 1.3065x over previous
#include <cuda_runtime.h>
#include <cuda_bf16.h>
#include <mma.h>
#include <cstdint>

using namespace nvcuda;

// EGCL: N_NODES=20000, N_EDGES=640000, FEAT=HID=128
#define TPB   256
#define HID   128
#define MAXN  20000
#define TILE  128

#define AST   136                 // bf16 image stride; 272B mod 128 = 16 -> conflict-free LDSM
#define CST   132                 // float C stride; 528B
#define IMG_B (128 * AST * 2)     // 34816 B per bf16 image
#define PANEL_B (2 * IMG_B)       // 69632 B per weight panel (hi+lo)

// ---------------- device scratch ----------------
__device__ float g_magg [(size_t)MAXN * HID];
__device__ float g_shift[(size_t)MAXN * 3];
// 9 panels: 0=pe_w0[0:128) 1=pe_w0[128:256) 2=pe_w1 3=px_w0 4=px_w1
//           5=ph_w0[0:128) 6=ph_w0[128:256) 7=ph_w1 8=ph_w2
__device__ unsigned char g_wimg[9 * PANEL_B];

// ---------------- helpers ----------------
__device__ __forceinline__ float tanh_ap(float x){
    float t; asm("tanh.approx.f32 %0, %1;" : "=f"(t) : "f"(x)); return t;
}
__device__ __forceinline__ float silu_f(float x){
    float t = tanh_ap(0.5f * x);
    return fmaf(0.5f * x, t, 0.5f * x);
}
__device__ __forceinline__ float sigmoid_f(float x){
    return fmaf(0.5f, tanh_ap(0.5f * x), 0.5f);
}
__device__ __forceinline__ void red4(float* p, float a, float b, float c, float d){
    asm volatile("red.global.add.v4.f32 [%0], {%1,%2,%3,%4};"
                 :: "l"(p), "f"(a), "f"(b), "f"(c), "f"(d) : "memory");
}
__device__ __forceinline__ uint32_t smem_u32(const void* p){
    uint32_t a; asm("{ .reg .u64 t; cvta.to.shared.u64 t, %1; cvt.u32.u64 %0, t; }" : "=r"(a) : "l"(p));
    return a;
}
// pack 2 floats -> bf16x2 hi + bf16x2 lo (split precision)
__device__ __forceinline__ uint32_t pack2(float a, float b, uint32_t &l2){
    uint32_t h2; asm("cvt.rn.bf16x2.f32 %0, %1, %2;" : "=r"(h2) : "f"(b), "f"(a));
    float fa = __uint_as_float(h2 << 16);
    float fb = __uint_as_float(h2 & 0xffff0000u);
    float ra = a - fa, rb = b - fb;
    asm("cvt.rn.bf16x2.f32 %0, %1, %2;" : "=r"(l2) : "f"(rb), "f"(ra));
    return h2;
}
__device__ __forceinline__ uint32_t pack2h(float a, float b){
    uint32_t h2; asm("cvt.rn.bf16x2.f32 %0, %1, %2;" : "=r"(h2) : "f"(b), "f"(a));
    return h2;
}
#define CP_COMMIT()  asm volatile("cp.async.commit_group;" ::: "memory")
#define CP_WAIT(n)   asm volatile("cp.async.wait_group %0;" :: "n"(n) : "memory")

// ---------------- wmma ----------------
typedef wmma::fragment<wmma::matrix_a, 16,16,16, __nv_bfloat16, wmma::row_major> FragA;
typedef wmma::fragment<wmma::matrix_b, 16,16,16, __nv_bfloat16, wmma::row_major> FragB;
typedef wmma::fragment<wmma::accumulator, 16,16,16, float> FragC;

__device__ __forceinline__ void fill0(FragC (&acc)[2][4]){
    #pragma unroll
    for (int mt = 0; mt < 2; mt++)
        #pragma unroll
        for (int nt = 0; nt < 4; nt++)
            wmma::fill_fragment(acc[mt][nt], 0.0f);
}

// K=128 GEMM, 3 bf16 products (emulated fp32). warp tile 32x64.
__device__ __forceinline__ void gemm_step3(const __nv_bfloat16* Ah, const __nv_bfloat16* Al,
                                           const unsigned char* panel,
                                           FragC (&acc)[2][4], int wr, int wc){
    const __nv_bfloat16* Bh = (const __nv_bfloat16*)panel;
    const __nv_bfloat16* Bl = (const __nv_bfloat16*)(panel + IMG_B);
    #pragma unroll
    for (int kt = 0; kt < 8; kt++){
        FragA ah[2], al[2];
        #pragma unroll
        for (int mt = 0; mt < 2; mt++){
            int row = wr * 32 + mt * 16;
            wmma::load_matrix_sync(ah[mt], Ah + row * AST + kt * 16, AST);
            wmma::load_matrix_sync(al[mt], Al + row * AST + kt * 16, AST);
        }
        #pragma unroll
        for (int nt = 0; nt < 4; nt++){
            int col = wc * 64 + nt * 16;
            FragB bh, bl;
            wmma::load_matrix_sync(bh, Bh + kt * 16 * AST + col, AST);
            wmma::load_matrix_sync(bl, Bl + kt * 16 * AST + col, AST);
            #pragma unroll
            for (int mt = 0; mt < 2; mt++){
                wmma::mma_sync(acc[mt][nt], ah[mt], bh, acc[mt][nt]);
                wmma::mma_sync(acc[mt][nt], ah[mt], bl, acc[mt][nt]);
                wmma::mma_sync(acc[mt][nt], al[mt], bh, acc[mt][nt]);
            }
        }
    }
}

// K=128 GEMM, 1 bf16 product (phi_x branch: error diluted ~2.5e-5x into output)
__device__ __forceinline__ void gemm_step1(const __nv_bfloat16* Ah,
                                           const unsigned char* panel,
                                           FragC (&acc)[2][4], int wr, int wc){
    const __nv_bfloat16* Bh = (const __nv_bfloat16*)panel;
    #pragma unroll
    for (int kt = 0; kt < 8; kt++){
        FragA ah[2];
        #pragma unroll
        for (int mt = 0; mt < 2; mt++)
            wmma::load_matrix_sync(ah[mt], Ah + (wr*32 + mt*16) * AST + kt * 16, AST);
        #pragma unroll
        for (int nt = 0; nt < 4; nt++){
            FragB bh;
            wmma::load_matrix_sync(bh, Bh + kt * 16 * AST + wc * 64 + nt * 16, AST);
            #pragma unroll
            for (int mt = 0; mt < 2; mt++)
                wmma::mma_sync(acc[mt][nt], ah[mt], bh, acc[mt][nt]);
        }
    }
}

__device__ __forceinline__ void store_c(float* C, FragC (&acc)[2][4], int wr, int wc){
    #pragma unroll
    for (int mt = 0; mt < 2; mt++)
        #pragma unroll
        for (int nt = 0; nt < 4; nt++)
            wmma::store_matrix_sync(C + (wr*32 + mt*16) * CST + wc*64 + nt*16,
                                    acc[mt][nt], CST, wmma::mem_row_major);
}

// ---- fused per-warp epilogues: store own C tile, syncwarp, read own rows (L1-hot),
// silu, write A. No cross-warp dependency -> saves one __syncthreads per use.
__device__ __forceinline__ void epi_fused_hl(FragC (&acc)[2][4], float* C,
        const float* bias, const float* wlen, const float* s_len,
        __nv_bfloat16* Ah, __nv_bfloat16* Al, int wr, int wc, int lane){
    store_c(C, acc, wr, wc);
    __syncwarp();
    const int row = wr * 32 + lane;
    const float* crow = C + row * CST + wc * 64;
    const float* b = bias + wc * 64;
    const float lenr = (wlen != nullptr) ? s_len[row] : 0.0f;
    const float* wl = (wlen != nullptr) ? (wlen + wc * 64) : nullptr;
    uint32_t* ih = (uint32_t*)(Ah + row * AST + wc * 64);
    uint32_t* il = (uint32_t*)(Al + row * AST + wc * 64);
    #pragma unroll
    for (int g = 0; g < 8; g++){
        float f[8];
        #pragma unroll
        for (int j = 0; j < 8; j++){
            int c = g * 8 + j;
            float x = crow[c] + b[c];
            if (wl) x += lenr * wl[c];
            f[j] = silu_f(x);
        }
        uint4 hi, lo;
        hi.x = pack2(f[0], f[1], lo.x);
        hi.y = pack2(f[2], f[3], lo.y);
        hi.z = pack2(f[4], f[5], lo.z);
        hi.w = pack2(f[6], f[7], lo.w);
        *(uint4*)(ih + g*4) = hi;
        *(uint4*)(il + g*4) = lo;
    }
}

__device__ __forceinline__ void epi_fused_hi(FragC (&acc)[2][4], float* C,
        const float* bias, __nv_bfloat16* Ah, int wr, int wc, int lane){
    store_c(C, acc, wr, wc);
    __syncwarp();
    const int row = wr * 32 + lane;
    const float* crow = C + row * CST + wc * 64;
    const float* b = bias + wc * 64;
    uint32_t* ih = (uint32_t*)(Ah + row * AST + wc * 64);
    #pragma unroll
    for (int g = 0; g < 8; g++){
        float f[8];
        #pragma unroll
        for (int j = 0; j < 8; j++)
            f[j] = silu_f(crow[g*8+j] + b[g*8+j]);
        uint4 hi;
        hi.x = pack2h(f[0], f[1]);
        hi.y = pack2h(f[2], f[3]);
        hi.z = pack2h(f[4], f[5]);
        hi.w = pack2h(f[6], f[7]);
        *(uint4*)(ih + g*4) = hi;
    }
}

// cp.async one 69632B panel: 256 threads x 17 x 16B
__device__ __forceinline__ void cp_panel(uint32_t dst, const unsigned char* src, int tid){
    #pragma unroll
    for (int i = 0; i < 17; i++){
        int off = (tid + i * 256) * 16;
        asm volatile("cp.async.cg.shared.global [%0], [%1], 16;"
                     :: "r"(dst + off), "l"(src + off) : "memory");
    }
}

// scaled 64-col half-row -> A hi/lo images at (r, half). src pre-offset by half*64.
__device__ __forceinline__ void gather_row(__nv_bfloat16* Ah, __nv_bfloat16* Al,
                                           const float* __restrict__ src, float sc,
                                           int r, int half){
    uint32_t* ih = (uint32_t*)(Ah + r * AST + half * 64);
    uint32_t* il = (uint32_t*)(Al + r * AST + half * 64);
    #pragma unroll
    for (int g = 0; g < 8; g++){
        float4 v0 = __ldg((const float4*)src + 2*g);
        float4 v1 = __ldg((const float4*)src + 2*g + 1);
        uint4 hi, lo;
        hi.x = pack2(v0.x*sc, v0.y*sc, lo.x);
        hi.y = pack2(v0.z*sc, v0.w*sc, lo.y);
        hi.z = pack2(v1.x*sc, v1.y*sc, lo.z);
        hi.w = pack2(v1.z*sc, v1.w*sc, lo.w);
        *(uint4*)(ih + g*4) = hi;
        *(uint4*)(il + g*4) = lo;
    }
}

// ---------------- zero / prep / dummy ----------------
__global__ void zero_kernel(int N){
    const int i = blockIdx.x * blockDim.x + threadIdx.x;
    const int stride = gridDim.x * blockDim.x;
    const int m4 = N * (HID / 4);
    float4 z4 = make_float4(0.f, 0.f, 0.f, 0.f);
    for (int j = i; j < m4; j += stride) ((float4*)g_magg)[j] = z4;
    for (int j = i; j < 3 * N; j += stride) g_shift[j] = 0.0f;
}

// shifts ncu's capture slot onto edge_kernel (profiling aid, ~2us)
__global__ void dummy_kernel(){}

__global__ void prep_kernel(const float* __restrict__ pe_w0, const float* __restrict__ pe_w1,
                            const float* __restrict__ px_w0, const float* __restrict__ px_w1,
                            const float* __restrict__ ph_w0, const float* __restrict__ ph_w1,
                            const float* __restrict__ ph_w2){
    int i = blockIdx.x * blockDim.x + threadIdx.x;   // 9 * 128 * 128
    if (i >= 9 * 128 * 128) return;
    int p = i >> 14, rem = i & 16383, n = rem >> 7, k = rem & 127;
    const float* W; int krow = k;
    switch (p){ case 0: W = pe_w0; break;
                case 1: W = pe_w0; krow = k + 128; break;
                case 2: W = pe_w1; break;
                case 3: W = px_w0; break;
                case 4: W = px_w1; break;
                case 5: W = ph_w0; break;
                case 6: W = ph_w0; krow = k + 128; break;
                case 7: W = ph_w1; break;
                default: W = ph_w2; }
    float w = __ldg(W + krow * HID + n);
    __nv_bfloat16 h = __float2bfloat16(w);
    __nv_bfloat16 l = __float2bfloat16(w - __bfloat162float(h));
    unsigned char* base = g_wimg + p * PANEL_B;
    *(__nv_bfloat16*)(base + (k * AST + n) * 2) = h;
    *(__nv_bfloat16*)(base + IMG_B + (k * AST + n) * 2) = l;
}

// ---------------- shared smem layout (bytes) ----------------
#define OFF_A     0
#define OFF_S0    69632
#define OFF_S1    139264
#define OFF_CONST 208896   // 7 x 512B const slots
#define OFF_LEN   212480
#define OFF_VX    212992
#define OFF_VY    213504
#define OFF_VZ    214016
#define OFF_RIDX  214528
#define OFF_SIDX  215040
#define OFF_MISC  215552
#define EDGE_SMEM 215560

// ---------------- edge kernel ----------------
__global__ void __launch_bounds__(TPB, 1) edge_kernel(
    const float* __restrict__ pos,   const float* __restrict__ feat,
    const float* __restrict__ pe_w0,
    const float* __restrict__ pe_b0, const float* __restrict__ pe_b1,
    const float* __restrict__ px_b0, const float* __restrict__ px_b1,
    const float* __restrict__ px_ow, const float* __restrict__ px_ob,
    const float* __restrict__ e_w,   const float* __restrict__ e_b,
    const int* __restrict__ senders, const int* __restrict__ recv, int E)
{
    extern __shared__ unsigned char sm[];
    const int tid  = threadIdx.x;
    const int wid  = tid >> 5;
    const int lane = tid & 31;
    const int wr = wid & 3, wc = wid >> 2;     // 4x2 warp grid, 32x64 tiles
    const int ebase = blockIdx.x * TILE;

    __nv_bfloat16* Ah = (__nv_bfloat16*)(sm + OFF_A);
    __nv_bfloat16* Al = (__nv_bfloat16*)(sm + OFF_A + IMG_B);
    float* c_pe_b0 = (float*)(sm + OFF_CONST);
    float* c_pe_b1 = (float*)(sm + OFF_CONST + 512);
    float* c_px_b0 = (float*)(sm + OFF_CONST + 1024);
    float* c_px_b1 = (float*)(sm + OFF_CONST + 1536);
    float* c_wlen  = (float*)(sm + OFF_CONST + 2048);
    float* c_pxow  = (float*)(sm + OFF_CONST + 2560);
    float* c_ew    = (float*)(sm + OFF_CONST + 3072);
    float* s_len   = (float*)(sm + OFF_LEN);
    float* s_vx    = (float*)(sm + OFF_VX);
    float* s_vy    = (float*)(sm + OFF_VY);
    float* s_vz    = (float*)(sm + OFF_VZ);
    int*   s_ridx  = (int*)  (sm + OFF_RIDX);
    int*   s_sidx  = (int*)  (sm + OFF_SIDX);
    float* s_misc  = (float*)(sm + OFF_MISC);

    const uint32_t smb = smem_u32(sm);

    cp_panel(smb + OFF_S0, g_wimg,           tid); CP_COMMIT();   // pe_w0 top
    cp_panel(smb + OFF_S1, g_wimg + PANEL_B, tid); CP_COMMIT();   // pe_w0 mid

    if (tid < 128){
        int e = ebase + tid;
        int ec = (e < E) ? e : 0;
        int s = __ldg(senders + ec), r = __ldg(recv + ec);
        float vx = __ldg(pos + 3*r + 0) - __ldg(pos + 3*s + 0);
        float vy = __ldg(pos + 3*r + 1) - __ldg(pos + 3*s + 1);
        float vz = __ldg(pos + 3*r + 2) - __ldg(pos + 3*s + 2);
        float n2 = vx*vx + vy*vy + vz*vz;
        s_len[tid] = (n2 > 0.0f) ? sqrtf(n2) : 0.0f;
        s_vx[tid] = vx; s_vy[tid] = vy; s_vz[tid] = vz;
        s_ridx[tid] = r; s_sidx[tid] = s;
    } else {
        int i = tid - 128;
        c_pe_b0[i] = __ldg(pe_b0 + i);
        c_pe_b1[i] = __ldg(pe_b1 + i);
        c_px_b0[i] = __ldg(px_b0 + i);
        c_px_b1[i] = __ldg(px_b1 + i);
        c_wlen[i]  = __ldg(pe_w0 + 256 * HID + i);
        c_pxow[i]  = __ldg(px_ow + i);
        c_ew[i]    = __ldg(e_w + i);
        if (i == 0){ s_misc[0] = __ldg(e_b); s_misc[1] = __ldg(px_ob); }
    }
    __syncthreads();

    const int r    = tid >> 1;
    const int half = tid & 1;
    const bool on  = (ebase + r < E);

    // ---- layer 1 (K=256 over two GEMMs) ----
    gather_row(Ah, Al, feat + (size_t)s_sidx[r] * HID + half*64, 1.0f, r, half);
    CP_WAIT(1);
    __syncthreads();

    FragC acc[2][4];
    fill0(acc);
    gemm_step3(Ah, Al, sm + OFF_S0, acc, wr, wc);
    __syncthreads();

    gather_row(Ah, Al, feat + (size_t)s_ridx[r] * HID + half*64, 1.0f, r, half);
    cp_panel(smb + OFF_S0, g_wimg + 2*PANEL_B, tid); CP_COMMIT();  // pe_w1 -> S0
    CP_WAIT(1);
    __syncthreads();

    gemm_step3(Ah, Al, sm + OFF_S1, acc, wr, wc);
    __syncthreads();

    // epi1 (fused per-warp): act1 = silu(C + pe_b0 + len*w_len) -> A (hi+lo)
    epi_fused_hl(acc, (float*)(sm + OFF_S1), c_pe_b0, c_wlen, s_len, Ah, Al, wr, wc, lane);
    __syncthreads();
    cp_panel(smb + OFF_S1, g_wimg + 3*PANEL_B, tid); CP_COMMIT();  // px_w0 -> S1
    CP_WAIT(1);                                  // pe_w1 resident
    __syncthreads();

    // ---- layer 2: m ----
    fill0(acc);
    gemm_step3(Ah, Al, sm + OFF_S0, acc, wr, wc);
    __syncthreads();
    store_c((float*)(sm + OFF_S0), acc, wr, wc);
    __syncthreads();

    // epi2 (cross-warp: gate row-reduction + RED aggregation); m -> A (hi only)
    {
        const float* crow = (float*)(sm + OFF_S0) + r * CST + half * 64;
        const float* bias = c_pe_b1 + half * 64;
        const float* ew   = c_ew    + half * 64;
        uint32_t* ih = (uint32_t*)(Ah + r * AST + half * 64);
        float m[64];
        float g = 0.0f;
        #pragma unroll
        for (int gq = 0; gq < 8; gq++){
            #pragma unroll
            for (int j = 0; j < 8; j++){
                int c = gq * 8 + j;
                float v = silu_f(crow[c] + bias[c]);
                m[c] = v;
                g = fmaf(v, ew[c], g);
            }
            uint4 hi;
            int c0 = gq * 8;
            hi.x = pack2h(m[c0+0], m[c0+1]);
            hi.y = pack2h(m[c0+2], m[c0+3]);
            hi.z = pack2h(m[c0+4], m[c0+5]);
            hi.w = pack2h(m[c0+6], m[c0+7]);
            *(uint4*)(ih + gq*4) = hi;
        }
        g += __shfl_xor_sync(0xffffffffu, g, 1);   // combine row halves
        float gate = sigmoid_f(g + s_misc[0]);
        if (on){
            float* mb = g_magg + (size_t)s_ridx[r] * HID + half * 64;
            #pragma unroll
            for (int j = 0; j < 64; j += 4)
                red4(mb + j, m[j]*gate, m[j+1]*gate, m[j+2]*gate, m[j+3]*gate);
        }
    }
    __syncthreads();
    cp_panel(smb + OFF_S0, g_wimg + 4*PANEL_B, tid); CP_COMMIT();  // px_w1 -> S0
    CP_WAIT(1);                                  // px_w0 resident
    __syncthreads();

    // ---- layer 3 (1-product) ----
    fill0(acc);
    gemm_step1(Ah, sm + OFF_S1, acc, wr, wc);
    __syncthreads();

    epi_fused_hi(acc, (float*)(sm + OFF_S1), c_px_b0, Ah, wr, wc, lane);
    CP_WAIT(0);                                  // px_w1 resident
    __syncthreads();

    // ---- layer 4 (1-product) + Dense(1) head ----
    fill0(acc);
    gemm_step1(Ah, sm + OFF_S0, acc, wr, wc);
    __syncthreads();
    store_c((float*)(sm + OFF_S0), acc, wr, wc);
    __syncthreads();

    {
        const float* crow = (float*)(sm + OFF_S0) + r * CST + half * 64;
        const float* bias = c_px_b1 + half * 64;
        const float* pw   = c_pxow  + half * 64;
        float a = 0.0f;
        #pragma unroll
        for (int c = 0; c < 64; c++)
            a = fmaf(silu_f(crow[c] + bias[c]), pw[c], a);
        a += __shfl_xor_sync(0xffffffffu, a, 1);
        if (half == 0 && on){
            float phi = a + s_misc[1];
            float cc = __fdividef(phi, 1.0f + s_len[r]);
            atomicAdd(g_shift + 3*s_ridx[r] + 0, cc * s_vx[r]);
            atomicAdd(g_shift + 3*s_ridx[r] + 1, cc * s_vy[r]);
            atomicAdd(g_shift + 3*s_ridx[r] + 2, cc * s_vz[r]);
        }
    }
}

// ---------------- node kernel (wmma, fused epilogues) ----------------
__global__ void __launch_bounds__(TPB, 1) node_kernel(
    const float* __restrict__ pos,   const float* __restrict__ feat,
    const float* __restrict__ ph_b0, const float* __restrict__ ph_b1,
    const float* __restrict__ ph_b2,
    float* __restrict__ out, int N)
{
    extern __shared__ unsigned char sm[];
    const int tid  = threadIdx.x;
    const int wid  = tid >> 5;
    const int lane = tid & 31;
    const int wr = wid & 3, wc = wid >> 2;
    const int base = blockIdx.x * TILE;

    __nv_bfloat16* Ah = (__nv_bfloat16*)(sm + OFF_A);
    __nv_bfloat16* Al = (__nv_bfloat16*)(sm + OFF_A + IMG_B);
    float* c_b0 = (float*)(sm + OFF_CONST);
    float* c_b1 = (float*)(sm + OFF_CONST + 512);
    float* c_b2 = (float*)(sm + OFF_CONST + 1024);

    const uint32_t smb = smem_u32(sm);

    cp_panel(smb + OFF_S0, g_wimg + 5*PANEL_B, tid); CP_COMMIT();   // ph_w0 top
    cp_panel(smb + OFF_S1, g_wimg + 6*PANEL_B, tid); CP_COMMIT();   // ph_w0 bottom

    if (tid < 128){
        c_b0[tid] = __ldg(ph_b0 + tid);
        c_b2[tid] = __ldg(ph_b2 + tid);
    } else {
        c_b1[tid - 128] = __ldg(ph_b1 + tid - 128);
    }
    __syncthreads();

    const int r    = tid >> 1;
    const int half = tid & 1;
    const int n    = base + r;
    const bool on  = (n < N);
    const int nc   = on ? n : (N - 1);
    const float inv_s = rsqrtf((float)(N - 1));

    // ---- layer 1 (K=256): [m_i*inv_s, h] @ ph_w0 ----
    gather_row(Ah, Al, g_magg + (size_t)nc * HID + half*64, inv_s, r, half);
    CP_WAIT(1);
    __syncthreads();

    FragC acc[2][4];
    fill0(acc);
    gemm_step3(Ah, Al, sm + OFF_S0, acc, wr, wc);
    __syncthreads();

    gather_row(Ah, Al, feat + (size_t)nc * HID + half*64, 1.0f, r, half);
    cp_panel(smb + OFF_S0, g_wimg + 7*PANEL_B, tid); CP_COMMIT();   // ph_w1
    CP_WAIT(1);
    __syncthreads();

    gemm_step3(Ah, Al, sm + OFF_S1, acc, wr, wc);
    __syncthreads();

    epi_fused_hl(acc, (float*)(sm + OFF_S1), c_b0, nullptr, nullptr, Ah, Al, wr, wc, lane);
    __syncthreads();
    cp_panel(smb + OFF_S1, g_wimg + 8*PANEL_B, tid); CP_COMMIT();   // ph_w2
    CP_WAIT(1);
    __syncthreads();

    // ---- layer 2 ----
    fill0(acc);
    gemm_step3(Ah, Al, sm + OFF_S0, acc, wr, wc);
    __syncthreads();

    epi_fused_hl(acc, (float*)(sm + OFF_S0), c_b1, nullptr, nullptr, Ah, Al, wr, wc, lane);
    CP_WAIT(0);
    __syncthreads();

    // ---- layer 3 (no activation) + fused final write ----
    fill0(acc);
    gemm_step3(Ah, Al, sm + OFF_S1, acc, wr, wc);
    __syncthreads();

    store_c((float*)(sm + OFF_S1), acc, wr, wc);
    __syncwarp();
    {
        const int row = wr * 32 + lane;
        const int nn  = base + row;
        if (nn < N){
            const float* crow = (float*)(sm + OFF_S1) + row * CST + wc * 64;
            const float* bias = c_b2 + wc * 64;
            const float* fr   = feat + (size_t)nn * HID + wc * 64;
            float* of = out + (size_t)3 * N + (size_t)nn * HID + wc * 64;
            #pragma unroll
            for (int g = 0; g < 16; g++){
                float4 f = __ldg((const float4*)fr + g);
                float4 o;
                o.x = crow[4*g+0] + bias[4*g+0] + f.x;
                o.y = crow[4*g+1] + bias[4*g+1] + f.y;
                o.z = crow[4*g+2] + bias[4*g+2] + f.z;
                o.w = crow[4*g+3] + bias[4*g+3] + f.w;
                *((float4*)of + g) = o;
            }
            if (wc == 0){
                const float inv_n = 1.0f / (float)(N - 1);
                out[3*nn+0] = __ldg(pos + 3*nn + 0) + g_shift[3*nn+0] * inv_n;
                out[3*nn+1] = __ldg(pos + 3*nn + 1) + g_shift[3*nn+1] * inv_n;
                out[3*nn+2] = __ldg(pos + 3*nn + 2) + g_shift[3*nn+2] * inv_n;
            }
        }
    }
}

// ---------------- launcher ----------------
extern "C" void kernel_launch(void* const* d_in, const int* in_sizes, int n_in,
                              void* d_out, int out_size)
{
    const float* pos   = (const float*)d_in[0];
    const float* feat  = (const float*)d_in[1];
    const float* pe_w0 = (const float*)d_in[2];
    const float* pe_b0 = (const float*)d_in[3];
    const float* pe_w1 = (const float*)d_in[4];
    const float* pe_b1 = (const float*)d_in[5];
    const float* px_w0 = (const float*)d_in[6];
    const float* px_b0 = (const float*)d_in[7];
    const float* px_w1 = (const float*)d_in[8];
    const float* px_b1 = (const float*)d_in[9];
    const float* px_ow = (const float*)d_in[10];
    const float* px_ob = (const float*)d_in[11];
    const float* e_w   = (const float*)d_in[12];
    const float* e_b   = (const float*)d_in[13];
    const float* ph_w0 = (const float*)d_in[14];
    const float* ph_b0 = (const float*)d_in[15];
    const float* ph_w1 = (const float*)d_in[16];
    const float* ph_b1 = (const float*)d_in[17];
    const float* ph_w2 = (const float*)d_in[18];
    const float* ph_b2 = (const float*)d_in[19];
    const int* senders = (const int*)d_in[20];
    const int* recv    = (const int*)d_in[21];

    const int N = in_sizes[0] / 3;
    const int E = in_sizes[20];

    cudaFuncSetAttribute(edge_kernel, cudaFuncAttributeMaxDynamicSharedMemorySize, EDGE_SMEM);
    cudaFuncSetAttribute(node_kernel, cudaFuncAttributeMaxDynamicSharedMemorySize, EDGE_SMEM);

    zero_kernel<<<512, 256>>>(N);
    prep_kernel<<<(9*128*128 + 255)/256, 256>>>(pe_w0, pe_w1, px_w0, px_w1,
                                                ph_w0, ph_w1, ph_w2);
    dummy_kernel<<<1, 1>>>();   // shifts ncu capture slot onto edge_kernel
    edge_kernel<<<(E + TILE - 1)/TILE, TPB, EDGE_SMEM>>>(
        pos, feat, pe_w0, pe_b0, pe_b1, px_b0, px_b1,
        px_ow, px_ob, e_w, e_b, senders, recv, E);
    node_kernel<<<(N + TILE - 1)/TILE, TPB, EDGE_SMEM>>>(
        pos, feat, ph_b0, ph_b1, ph_b2, (float*)d_out, N);
}